// round 16
// baseline (speedup 1.0000x reference)
#include <cuda_runtime.h>
#include <cuda_bf16.h>
#include <cstdint>
#include <math.h>

#define NB 32
#define NN 512
#define DD 256
#define INV_EPS 10.0f
#define TINYF 1e-16f
#define MARG (1.0f/512.0f)
#define ITERS 15
#define PGRID 128      // 32 clusters x 4 CTAs; 1 block/SM
#define PTHREADS 512

// ---------------- scratch (static __device__; no allocations) ----------------
static __device__ unsigned g_Ebf[(size_t)NB*NN*NN/2];    // 16 MB E as packed bf16x2

// ---------------- helpers -----------------------------------------------------
__device__ __forceinline__ unsigned smem_u32(const void* p) {
    unsigned a;
    asm("{ .reg .u64 t; cvta.to.shared.u64 t, %1; cvt.u32.u64 %0, t; }"
        : "=r"(a) : "l"(p));
    return a;
}
__device__ __forceinline__ float dsmem_ld(unsigned local_addr, unsigned rank) {
    unsigned rem; float v;
    asm volatile("mapa.shared::cluster.u32 %0, %1, %2;" : "=r"(rem)
                 : "r"(local_addr), "r"(rank));
    asm volatile("ld.shared::cluster.f32 %0, [%1];" : "=f"(v) : "r"(rem));
    return v;
}
__device__ __forceinline__ unsigned f2tf32(float f) {
    unsigned r;
    asm("cvt.rna.tf32.f32 %0, %1;" : "=r"(r) : "f"(f));
    return r;
}
#define CLUSTER_BAR() do { \
    asm volatile("barrier.cluster.arrive.aligned;" ::: "memory"); \
    asm volatile("barrier.cluster.wait.aligned;"   ::: "memory"); } while (0)

// ---------------- smem layout -------------------------------------------------
// GEMM phase: A plane [128][260] f32 (133120 B) overlaps the E region + part of
// colp (both dead during GEMM).  Iter phase: E tile back at 0 (from g_Ebf).
#define SM_A     0                            // gemm: 133120 B
#define SM_E     0                            // iter: 131072 B
#define SM_COLP  133120                       // iter: [16][512] col partials
#define SM_COLR  (SM_COLP + 32768)            // iter: [2][512]; phase0: y-norm slice
#define SM_W     (SM_COLR + 4096)             // iter: w[512]; gemm: ryAll[512]
#define SM_Q     (SM_W + 2048)
#define SM_P     (SM_Q + 2048)
#define SM_SU    (SM_P + 512)                 // gemm: rx[128]
#define SM_CRED  (SM_SU + 512)
#define SM_B0    (SM_CRED + 128)              // gemm: Bs0[128][36] f32
#define SM_B1    (SM_B0 + 18432)
#define SM_TOT   (SM_B1 + 18432)              // 212096 B (< 227 KB)

// ---------------- fused kernel: GEMM + Sinkhorn + epilogue -------------------
__global__ void __cluster_dims__(4, 1, 1) __launch_bounds__(PTHREADS, 1)
sink_kernel(float* __restrict__ cost, float* __restrict__ pi,
            float* __restrict__ C,
            const float* __restrict__ x, const float* __restrict__ y) {
    extern __shared__ unsigned char sm[];
    float* Afl    = (float*)(sm + SM_A);         // gemm: [128][260]
    unsigned* Eu  = (unsigned*)(sm + SM_E);      // iter: [128][256] bf16x2 words
    float* colp   = (float*)(sm + SM_COLP);      // [16][512]
    float* colr   = (float*)(sm + SM_COLR);      // [2][512]
    float* w      = (float*)(sm + SM_W);         // [512]
    float* q      = (float*)(sm + SM_Q);         // [512]
    float* p      = (float*)(sm + SM_P);         // [128]
    float* su     = (float*)(sm + SM_SU);        // [128]  (gemm: rx)
    float* cred   = (float*)(sm + SM_CRED);      // [16]
    float* rxs    = su;
    float* ryAll  = w;                           // 512 y-norms during gemm

    int g = blockIdx.x, b = g >> 2;
    unsigned rank;
    asm("mov.u32 %0, %%cluster_ctarank;" : "=r"(rank));
    int row0 = (int)rank * 128;
    int t = threadIdx.x, warp = t >> 5, lane = t & 31;
    unsigned sb = smem_u32(sm);

    // ================= Phase 0: row norms (x local; y exchanged) ============
    if (t < 256) {
        int r = t & 127;
        const float4* row = (const float4*)
            ((t < 128 ? x : y) + ((size_t)(b*NN + row0 + r)) * DD);
        float s0 = 0.f, s1 = 0.f;
        #pragma unroll
        for (int j = 0; j < 32; j++) {
            float4 v0 = row[2*j], v1 = row[2*j+1];
            s0 += v0.x*v0.x + v0.y*v0.y + v0.z*v0.z + v0.w*v0.w;
            s1 += v1.x*v1.x + v1.y*v1.y + v1.z*v1.z + v1.w*v1.w;
        }
        float r2 = rsqrtf(s0 + s1);
        if (t < 128) rxs[r] = r2;
        else         colr[r] = r2;               // stage local y-norm slice
    }
    __syncthreads();
    CLUSTER_BAR();
    ryAll[t] = dsmem_ld(sb + SM_COLR + (unsigned)(t & 127) * 4,
                        (unsigned)(t >> 7));
    CLUSTER_BAR();   // protect colr slices until every CTA has read them

    // ================= Phase 1: GEMM (A-resident, B double-buffered) ========
    {
        int wm = (warp >> 2) * 32;               // warp m offset 0..96
        int wn = (warp & 3) * 32;                // warp n offset 0..96
        int arow = t >> 2;                       // 0..127 staging row
        int ac8  = (t & 3) * 8;                  // B staging col chunk (floats)

        // ---- stage A ONCE: thread t -> row t>>2, cols (t&3)*64..+64 ----
        {
            int acol = (t & 3) * 64;
            const float4* xr = (const float4*)
                (x + ((size_t)(b*NN + row0 + arow)) * DD + acol);
            float* Ar = Afl + arow * 260 + acol;
            #pragma unroll
            for (int j = 0; j < 16; j++) {
                float4 v = xr[j];
                float4 wv;
                wv.x = __uint_as_float(f2tf32(v.x));
                wv.y = __uint_as_float(f2tf32(v.y));
                wv.z = __uint_as_float(f2tf32(v.z));
                wv.w = __uint_as_float(f2tf32(v.w));
                *(float4*)(Ar + j*4) = wv;
            }
        }
        __syncthreads();

        unsigned* Ew = g_Ebf + (size_t)b * (NN*NN/2) + (size_t)row0 * 256;
        size_t cb = (size_t)b * NN * NN + (size_t)row0 * NN;

        for (int nt0 = 0; nt0 < 4; nt0++) {
            int n0 = nt0 * 128;
            const float* yrow = y + ((size_t)(b*NN + n0 + arow)) * DD;

            float acc[2][4][4];
            #pragma unroll
            for (int i=0;i<2;i++)
                #pragma unroll
                for (int j=0;j<4;j++)
                    #pragma unroll
                    for (int k=0;k<4;k++) acc[i][j][k] = 0.f;

            // stage B slab 0
            float4 pb0 = *(const float4*)(yrow + ac8);
            float4 pb1 = *(const float4*)(yrow + ac8 + 4);
            {
                float (*Bs)[36] = (float(*)[36])(sm + SM_B0);
                Bs[arow][ac8+0] = __uint_as_float(f2tf32(pb0.x));
                Bs[arow][ac8+1] = __uint_as_float(f2tf32(pb0.y));
                Bs[arow][ac8+2] = __uint_as_float(f2tf32(pb0.z));
                Bs[arow][ac8+3] = __uint_as_float(f2tf32(pb0.w));
                Bs[arow][ac8+4] = __uint_as_float(f2tf32(pb1.x));
                Bs[arow][ac8+5] = __uint_as_float(f2tf32(pb1.y));
                Bs[arow][ac8+6] = __uint_as_float(f2tf32(pb1.z));
                Bs[arow][ac8+7] = __uint_as_float(f2tf32(pb1.w));
            }
            __syncthreads();

            for (int s = 0; s < 8; s++) {
                if (s < 7) {    // prefetch next B slab into 8 registers
                    int k0 = (s + 1) * 32;
                    pb0 = *(const float4*)(yrow + k0 + ac8);
                    pb1 = *(const float4*)(yrow + k0 + ac8 + 4);
                }
                float (*Bs)[36] = (float(*)[36])(sm + ((s & 1) ? SM_B1 : SM_B0));
                #pragma unroll
                for (int ks = 0; ks < 4; ks++) {
                    int kcb = ks * 8 + (lane & 3);
                    int kca = s * 32 + kcb;
                    unsigned bf[4][2];
                    #pragma unroll
                    for (int nx = 0; nx < 4; nx++) {
                        int nbr = wn + nx*8 + (lane >> 2);
                        bf[nx][0] = __float_as_uint(Bs[nbr][kcb]);
                        bf[nx][1] = __float_as_uint(Bs[nbr][kcb + 4]);
                    }
                    #pragma unroll
                    for (int mt = 0; mt < 2; mt++) {
                        int ma = wm + mt*16 + (lane >> 2);
                        unsigned fa0 = __float_as_uint(Afl[ma*260 + kca]);
                        unsigned fa1 = __float_as_uint(Afl[(ma+8)*260 + kca]);
                        unsigned fa2 = __float_as_uint(Afl[ma*260 + kca + 4]);
                        unsigned fa3 = __float_as_uint(Afl[(ma+8)*260 + kca + 4]);
                        #pragma unroll
                        for (int nx = 0; nx < 4; nx++) {
                            asm volatile(
                                "mma.sync.aligned.m16n8k8.row.col.f32.tf32.tf32.f32 "
                                "{%0,%1,%2,%3}, {%4,%5,%6,%7}, {%8,%9}, {%0,%1,%2,%3};"
                                : "+f"(acc[mt][nx][0]), "+f"(acc[mt][nx][1]),
                                  "+f"(acc[mt][nx][2]), "+f"(acc[mt][nx][3])
                                : "r"(fa0), "r"(fa1), "r"(fa2), "r"(fa3),
                                  "r"(bf[nx][0]), "r"(bf[nx][1]));
                        }
                    }
                }
                __syncthreads();
                if (s < 7) {
                    float (*Bn)[36] = (float(*)[36])(sm + (((s+1) & 1) ? SM_B1 : SM_B0));
                    Bn[arow][ac8+0] = __uint_as_float(f2tf32(pb0.x));
                    Bn[arow][ac8+1] = __uint_as_float(f2tf32(pb0.y));
                    Bn[arow][ac8+2] = __uint_as_float(f2tf32(pb0.z));
                    Bn[arow][ac8+3] = __uint_as_float(f2tf32(pb0.w));
                    Bn[arow][ac8+4] = __uint_as_float(f2tf32(pb1.x));
                    Bn[arow][ac8+5] = __uint_as_float(f2tf32(pb1.y));
                    Bn[arow][ac8+6] = __uint_as_float(f2tf32(pb1.z));
                    Bn[arow][ac8+7] = __uint_as_float(f2tf32(pb1.w));
                    __syncthreads();
                }
            }
            // epilogue: C fp32 -> gmem, E bf16 -> gmem scratch
            #pragma unroll
            for (int mt = 0; mt < 2; mt++) {
                #pragma unroll
                for (int nx = 0; nx < 4; nx++) {
                    int ml = wm + mt*16 + (lane >> 2);
                    int nl = wn + nx*8 + (lane & 3)*2;
                    float rx0 = rxs[ml], rx2 = rxs[ml + 8];
                    float ry0 = ryAll[n0 + nl], ry1 = ryAll[n0 + nl + 1];
                    float c0 = 1.0f - acc[mt][nx][0] * rx0 * ry0;
                    float c1 = 1.0f - acc[mt][nx][1] * rx0 * ry1;
                    float c2 = 1.0f - acc[mt][nx][2] * rx2 * ry0;
                    float c3 = 1.0f - acc[mt][nx][3] * rx2 * ry1;
                    *(float2*)&C[cb + (size_t)ml*NN + n0 + nl]     = make_float2(c0, c1);
                    *(float2*)&C[cb + (size_t)(ml+8)*NN + n0 + nl] = make_float2(c2, c3);
                    __nv_bfloat162 e01 = __floats2bfloat162_rn(__expf(-INV_EPS*c0), __expf(-INV_EPS*c1));
                    __nv_bfloat162 e23 = __floats2bfloat162_rn(__expf(-INV_EPS*c2), __expf(-INV_EPS*c3));
                    Ew[ml*256 + ((n0 + nl) >> 1)]     = *(unsigned*)&e01;
                    Ew[(ml+8)*256 + ((n0 + nl) >> 1)] = *(unsigned*)&e23;
                }
            }
        }
    }
    __syncthreads();

    // ================= Phase 2: Sinkhorn iterations ==========================
    // prologue: reload this CTA's bf16 E tile into smem (A plane now dead)
    {
        const uint4* Eg4 = (const uint4*)(g_Ebf + ((size_t)b * NN + row0) * 256);
        uint4* Es4 = (uint4*)Eu;
        #pragma unroll
        for (int i = t; i < 8192; i += PTHREADS) Es4[i] = Eg4[i];
    }
    if (t < 512) { w[t] = 1.f; q[t] = 1.f; }
    if (t < 128) p[t] = 1.f;
    __syncthreads();

    for (int it = 0; it < ITERS; it++) {
        float wreg[16];
        #pragma unroll
        for (int k = 0; k < 8; k++) {
            float2 wp = *(const float2*)&w[2*lane + 64*k];
            wreg[2*k] = wp.x; wreg[2*k+1] = wp.y;
        }
        float colacc[16];
        #pragma unroll
        for (int i = 0; i < 16; i++) colacc[i] = 0.f;

        #pragma unroll
        for (int rg = 0; rg < 4; rg++) {
            int rowA = warp * 8 + rg * 2;
            int rowB = rowA + 1;
            const unsigned* EA = &Eu[rowA * 256];
            const unsigned* EB = &Eu[rowB * 256];
            unsigned ea[8], eb[8];
            #pragma unroll
            for (int k = 0; k < 8; k++) ea[k] = EA[lane + 32*k];
            #pragma unroll
            for (int k = 0; k < 8; k++) eb[k] = EB[lane + 32*k];

            float dA0=0.f, dA1=0.f, dB0=0.f, dB1=0.f;
            #pragma unroll
            for (int k = 0; k < 8; k++) {
                dA0 += __uint_as_float(ea[k] << 16)         * wreg[2*k];
                dA1 += __uint_as_float(ea[k] & 0xffff0000u) * wreg[2*k+1];
                dB0 += __uint_as_float(eb[k] << 16)         * wreg[2*k];
                dB1 += __uint_as_float(eb[k] & 0xffff0000u) * wreg[2*k+1];
            }
            float dA = dA0 + dA1, dB = dB0 + dB1;
            #pragma unroll
            for (int o = 16; o; o >>= 1) {
                dA += __shfl_xor_sync(0xffffffffu, dA, o);
                dB += __shfl_xor_sync(0xffffffffu, dB, o);
            }
            float pA = p[rowA], pB = p[rowB];
            float uA = MARG / (pA * dA + TINYF);
            float uB = MARG / (pB * dB + TINYF);
            float pnA = pA * uA, pnB = pB * uB;
            if (lane == 0) {
                p[rowA] = pnA; p[rowB] = pnB;
                if (it == ITERS - 1) { su[rowA] = uA * pnA; su[rowB] = uB * pnB; }
            }
            #pragma unroll
            for (int k = 0; k < 8; k++) {
                colacc[2*k]   += __uint_as_float(ea[k] << 16)         * pnA
                               + __uint_as_float(eb[k] << 16)         * pnB;
                colacc[2*k+1] += __uint_as_float(ea[k] & 0xffff0000u) * pnA
                               + __uint_as_float(eb[k] & 0xffff0000u) * pnB;
            }
        }
        #pragma unroll
        for (int k = 0; k < 8; k++)
            *(float2*)&colp[warp * 512 + 2*lane + 64*k] =
                make_float2(colacc[2*k], colacc[2*k+1]);
        __syncthreads();
        if (t < 512) {
            float s = 0.f;
            #pragma unroll
            for (int j = 0; j < 16; j++) s += colp[j * 512 + t];
            colr[(it & 1) * 512 + t] = s;
        }
        CLUSTER_BAR();
        if (t < 512) {
            unsigned addr = sb + SM_COLR + (unsigned)(it & 1) * 2048 + t * 4;
            float s0 = dsmem_ld(addr, 0);
            float s1 = dsmem_ld(addr, 1);
            float s2 = dsmem_ld(addr, 2);
            float s3 = dsmem_ld(addr, 3);
            float tot = (s0 + s1) + (s2 + s3);
            float qold = q[t];
            float v = MARG / (qold * tot + TINYF);
            float qn = qold * v;
            q[t] = qn;
            w[t] = qn * v;
        }
        __syncthreads();
    }

    // ================= Phase 3: pi + cost epilogue ===========================
    size_t base = ((size_t)b * NN + row0) * NN;
    float csum = 0.f;
    for (int r = 0; r < 8; r++) {
        int row = warp * 8 + r;
        float s_u = su[row];
        const float4* C4 = (const float4*)(C + base + (size_t)row * NN);
        float4*       P4 = (float4*)(pi + base + (size_t)row * NN);
        #pragma unroll
        for (int k = 0; k < 4; k++) {
            int idx = lane + 32*k;
            float4 cc = C4[idx];
            float4 wv = *(const float4*)&w[4*lane + 128*k];
            float4 pv;
            pv.x = __expf(-INV_EPS*cc.x) * s_u * wv.x;
            pv.y = __expf(-INV_EPS*cc.y) * s_u * wv.y;
            pv.z = __expf(-INV_EPS*cc.z) * s_u * wv.z;
            pv.w = __expf(-INV_EPS*cc.w) * s_u * wv.w;
            csum += pv.x*cc.x + pv.y*cc.y + pv.z*cc.z + pv.w*cc.w;
            asm volatile("st.global.cs.v4.f32 [%0], {%1,%2,%3,%4};"
                         :: "l"(P4 + idx), "f"(pv.x), "f"(pv.y), "f"(pv.z), "f"(pv.w)
                         : "memory");
        }
    }
    #pragma unroll
    for (int o = 16; o; o >>= 1) csum += __shfl_xor_sync(0xffffffffu, csum, o);
    if (lane == 0) cred[warp] = csum;
    __syncthreads();
    if (t == 0) {
        float s = 0.f;
        #pragma unroll
        for (int i = 0; i < 16; i++) s += cred[i];
        cred[0] = s;
    }
    CLUSTER_BAR();
    if (rank == 0 && t == 0) {
        unsigned addr = sb + SM_CRED;
        float s0 = dsmem_ld(addr, 0);
        float s1 = dsmem_ld(addr, 1);
        float s2 = dsmem_ld(addr, 2);
        float s3 = dsmem_ld(addr, 3);
        cost[b] = (s0 + s1) + (s2 + s3);
    }
    CLUSTER_BAR();
}

// ---------------- launch ------------------------------------------------------
extern "C" void kernel_launch(void* const* d_in, const int* in_sizes, int n_in,
                              void* d_out, int out_size) {
    const float* x = (const float*)d_in[0];
    const float* y = (const float*)d_in[1];
    float* out  = (float*)d_out;
    float* cost = out;
    float* pi   = out + NB;
    float* C    = out + NB + (size_t)NB * NN * NN;

    static int smem_set = 0;
    if (!smem_set) {
        cudaFuncSetAttribute(sink_kernel,
                             cudaFuncAttributeMaxDynamicSharedMemorySize, SM_TOT);
        smem_set = 1;
    }

    sink_kernel<<<PGRID, PTHREADS, SM_TOT>>>(cost, pi, C, x, y);
}

// round 17
// speedup vs baseline: 1.2753x; 1.2753x over previous
#include <cuda_runtime.h>
#include <cuda_bf16.h>
#include <cstdint>
#include <math.h>

#define NB 32
#define NN 512
#define DD 256
#define INV_EPS 10.0f
#define TINYF 1e-16f
#define MARG (1.0f/512.0f)
#define ITERS 15
#define PGRID 128      // 32 clusters x 4 CTAs; 1 block/SM
#define PTHREADS 512

// ---------------- scratch (static __device__; no allocations) ----------------
static __device__ unsigned g_Ebf[(size_t)NB*NN*NN/2];    // 16 MB E as packed bf16x2

// ---------------- helpers -----------------------------------------------------
__device__ __forceinline__ unsigned smem_u32(const void* p) {
    unsigned a;
    asm("{ .reg .u64 t; cvta.to.shared.u64 t, %1; cvt.u32.u64 %0, t; }"
        : "=r"(a) : "l"(p));
    return a;
}
__device__ __forceinline__ float dsmem_ld(unsigned local_addr, unsigned rank) {
    unsigned rem; float v;
    asm volatile("mapa.shared::cluster.u32 %0, %1, %2;" : "=r"(rem)
                 : "r"(local_addr), "r"(rank));
    asm volatile("ld.shared::cluster.f32 %0, [%1];" : "=f"(v) : "r"(rem));
    return v;
}
__device__ __forceinline__ unsigned f2tf32(float f) {
    unsigned r;
    asm("cvt.rna.tf32.f32 %0, %1;" : "=r"(r) : "f"(f));
    return r;
}
#define CLUSTER_BAR() do { \
    asm volatile("barrier.cluster.arrive.aligned;" ::: "memory"); \
    asm volatile("barrier.cluster.wait.aligned;"   ::: "memory"); } while (0)

// ---------------- 1) standalone tf32 GEMM, double-buffered + reg prefetch ----
// BM=128, BN=64, BK=32; 256 threads; 2 CTAs/SM.  C = 1 - dot*rx*ry;
// E = bf16(exp(-10C)) -> g_Ebf.  Row norms accumulated during staging.
#define GAS0 0
#define GAS1 18432
#define GBS0 36864
#define GBS1 46080
#define GRAN 55296
#define GRBN (GRAN + 512)
#define GTOT (GRBN + 256 + 64)

__global__ void __launch_bounds__(256, 2) gemm_kernel(float* __restrict__ Cout,
                                                      const float* __restrict__ x,
                                                      const float* __restrict__ y) {
    extern __shared__ unsigned char gsm[];
    float* ran = (float*)(gsm + GRAN);
    float* rbn = (float*)(gsm + GRBN);
    int b  = blockIdx.z;
    int m0 = blockIdx.y * 128, n0 = blockIdx.x * 64;
    const float* A = x + (size_t)b * NN * DD;
    const float* B = y + (size_t)b * NN * DD;
    int t = threadIdx.x, lane = t & 31, warp = t >> 5;
    int wm = (warp >> 1) * 32;      // warp m offset (0,32,64,96)
    int wn = (warp & 1) * 32;       // warp n offset (0,32)
    int lr = t >> 3;                // 0..31 staging row
    int lc = (t & 7) * 4;           // 0..28 staging col

    float ssA[4] = {0,0,0,0};
    float ssB[2] = {0,0};

    float acc[2][4][4];
    #pragma unroll
    for (int i=0;i<2;i++)
        #pragma unroll
        for (int j=0;j<4;j++)
            #pragma unroll
            for (int k=0;k<4;k++) acc[i][j][k] = 0.f;

    float4 pa[4], pb[2];
    // ---- load + stage slab 0 ----
    #pragma unroll
    for (int i = 0; i < 4; i++)
        pa[i] = *(const float4*)(A + (size_t)(m0 + lr + 32*i) * DD + lc);
    #pragma unroll
    for (int i = 0; i < 2; i++)
        pb[i] = *(const float4*)(B + (size_t)(n0 + lr + 32*i) * DD + lc);
    {
        float (*As)[36] = (float(*)[36])(gsm + GAS0);
        float (*Bs)[36] = (float(*)[36])(gsm + GBS0);
        #pragma unroll
        for (int i = 0; i < 4; i++) {
            float4 v = pa[i];
            ssA[i] += v.x*v.x + v.y*v.y + v.z*v.z + v.w*v.w;
            As[lr + 32*i][lc+0] = __uint_as_float(f2tf32(v.x));
            As[lr + 32*i][lc+1] = __uint_as_float(f2tf32(v.y));
            As[lr + 32*i][lc+2] = __uint_as_float(f2tf32(v.z));
            As[lr + 32*i][lc+3] = __uint_as_float(f2tf32(v.w));
        }
        #pragma unroll
        for (int i = 0; i < 2; i++) {
            float4 v = pb[i];
            ssB[i] += v.x*v.x + v.y*v.y + v.z*v.z + v.w*v.w;
            Bs[lr + 32*i][lc+0] = __uint_as_float(f2tf32(v.x));
            Bs[lr + 32*i][lc+1] = __uint_as_float(f2tf32(v.y));
            Bs[lr + 32*i][lc+2] = __uint_as_float(f2tf32(v.z));
            Bs[lr + 32*i][lc+3] = __uint_as_float(f2tf32(v.w));
        }
    }

    for (int s = 0; s < 8; s++) {
        __syncthreads();   // buffer (s&1) staged; prior reads of buffer (s&1) done
        if (s < 7) {       // prefetch next slab into registers (hidden by mma)
            int k0 = (s + 1) * 32;
            #pragma unroll
            for (int i = 0; i < 4; i++)
                pa[i] = *(const float4*)(A + (size_t)(m0 + lr + 32*i) * DD + k0 + lc);
            #pragma unroll
            for (int i = 0; i < 2; i++)
                pb[i] = *(const float4*)(B + (size_t)(n0 + lr + 32*i) * DD + k0 + lc);
        }
        float (*As)[36] = (float(*)[36])(gsm + ((s & 1) ? GAS1 : GAS0));
        float (*Bs)[36] = (float(*)[36])(gsm + ((s & 1) ? GBS1 : GBS0));
        #pragma unroll
        for (int ks = 0; ks < 4; ks++) {
            int kc = ks * 8 + (lane & 3);
            unsigned bf[4][2];
            #pragma unroll
            for (int nt = 0; nt < 4; nt++) {
                int nb = wn + nt*8 + (lane >> 2);
                bf[nt][0] = __float_as_uint(Bs[nb][kc]);
                bf[nt][1] = __float_as_uint(Bs[nb][kc + 4]);
            }
            #pragma unroll
            for (int mt = 0; mt < 2; mt++) {
                int ma = wm + mt*16 + (lane >> 2);
                unsigned a0 = __float_as_uint(As[ma    ][kc]);
                unsigned a1 = __float_as_uint(As[ma + 8][kc]);
                unsigned a2 = __float_as_uint(As[ma    ][kc + 4]);
                unsigned a3 = __float_as_uint(As[ma + 8][kc + 4]);
                #pragma unroll
                for (int nt = 0; nt < 4; nt++) {
                    asm volatile(
                        "mma.sync.aligned.m16n8k8.row.col.f32.tf32.tf32.f32 "
                        "{%0,%1,%2,%3}, {%4,%5,%6,%7}, {%8,%9}, {%0,%1,%2,%3};"
                        : "+f"(acc[mt][nt][0]), "+f"(acc[mt][nt][1]),
                          "+f"(acc[mt][nt][2]), "+f"(acc[mt][nt][3])
                        : "r"(a0), "r"(a1), "r"(a2), "r"(a3),
                          "r"(bf[nt][0]), "r"(bf[nt][1]));
                }
            }
        }
        if (s < 7) {       // stage prefetched slab into the OTHER buffer
            float (*An)[36] = (float(*)[36])(gsm + (((s+1) & 1) ? GAS1 : GAS0));
            float (*Bn)[36] = (float(*)[36])(gsm + (((s+1) & 1) ? GBS1 : GBS0));
            #pragma unroll
            for (int i = 0; i < 4; i++) {
                float4 v = pa[i];
                ssA[i] += v.x*v.x + v.y*v.y + v.z*v.z + v.w*v.w;
                An[lr + 32*i][lc+0] = __uint_as_float(f2tf32(v.x));
                An[lr + 32*i][lc+1] = __uint_as_float(f2tf32(v.y));
                An[lr + 32*i][lc+2] = __uint_as_float(f2tf32(v.z));
                An[lr + 32*i][lc+3] = __uint_as_float(f2tf32(v.w));
            }
            #pragma unroll
            for (int i = 0; i < 2; i++) {
                float4 v = pb[i];
                ssB[i] += v.x*v.x + v.y*v.y + v.z*v.z + v.w*v.w;
                Bn[lr + 32*i][lc+0] = __uint_as_float(f2tf32(v.x));
                Bn[lr + 32*i][lc+1] = __uint_as_float(f2tf32(v.y));
                Bn[lr + 32*i][lc+2] = __uint_as_float(f2tf32(v.z));
                Bn[lr + 32*i][lc+3] = __uint_as_float(f2tf32(v.w));
            }
        }
    }

    // reduce sum-of-squares across the 8 staging threads of each row
    #pragma unroll
    for (int o = 4; o; o >>= 1) {
        #pragma unroll
        for (int i = 0; i < 4; i++) ssA[i] += __shfl_xor_sync(0xffffffffu, ssA[i], o);
        #pragma unroll
        for (int i = 0; i < 2; i++) ssB[i] += __shfl_xor_sync(0xffffffffu, ssB[i], o);
    }
    if ((t & 7) == 0) {
        #pragma unroll
        for (int i = 0; i < 4; i++) ran[lr + 32*i] = rsqrtf(ssA[i]);
        #pragma unroll
        for (int i = 0; i < 2; i++) rbn[lr + 32*i] = rsqrtf(ssB[i]);
    }
    __syncthreads();

    size_t base = (size_t)b * NN * NN;
    unsigned* Ew = g_Ebf + (size_t)b * (NN * NN / 2);
    #pragma unroll
    for (int mt = 0; mt < 2; mt++) {
        #pragma unroll
        for (int nt = 0; nt < 4; nt++) {
            int ml = wm + mt*16 + (lane >> 2);
            int nl = wn + nt*8 + (lane & 3)*2;
            int m = m0 + ml, n = n0 + nl;
            float r0 = ran[ml];
            float r2 = ran[ml + 8];
            float rb0 = rbn[nl], rb1 = rbn[nl + 1];
            float c0 = 1.0f - acc[mt][nt][0] * r0 * rb0;
            float c1 = 1.0f - acc[mt][nt][1] * r0 * rb1;
            float c2 = 1.0f - acc[mt][nt][2] * r2 * rb0;
            float c3 = 1.0f - acc[mt][nt][3] * r2 * rb1;
            *(float2*)&Cout[base + (size_t)m*NN + n]     = make_float2(c0, c1);
            *(float2*)&Cout[base + (size_t)(m+8)*NN + n] = make_float2(c2, c3);
            __nv_bfloat162 p01 = __floats2bfloat162_rn(__expf(-INV_EPS*c0), __expf(-INV_EPS*c1));
            __nv_bfloat162 p23 = __floats2bfloat162_rn(__expf(-INV_EPS*c2), __expf(-INV_EPS*c3));
            Ew[m*256 + (n >> 1)]     = *(unsigned*)&p01;
            Ew[(m+8)*256 + (n >> 1)] = *(unsigned*)&p23;
        }
    }
}

// ---------------- 2) persistent Sinkhorn kernel (cluster of 4) ---------------
#define SM_E     0
#define SM_COLP  131072                       // 16 warps x 512 floats = 32768
#define SM_COLR  (SM_COLP + 32768)            // 2 x 512 floats (double buffer)
#define SM_W     (SM_COLR + 4096)
#define SM_Q     (SM_W + 2048)
#define SM_P     (SM_Q + 2048)
#define SM_SU    (SM_P + 512)
#define SM_CRED  (SM_SU + 512)
#define SM_TOT   (SM_CRED + 64 + 64)

__global__ void __cluster_dims__(4, 1, 1) __launch_bounds__(PTHREADS, 1)
sink_kernel(float* __restrict__ cost, float* __restrict__ pi,
            const float* __restrict__ C) {
    extern __shared__ unsigned char sm[];
    unsigned* Eu  = (unsigned*)(sm + SM_E);      // [128][256] words (2 bf16/word)
    float* colp   = (float*)(sm + SM_COLP);      // [16][512]
    float* colr   = (float*)(sm + SM_COLR);      // [2][512]
    float* w      = (float*)(sm + SM_W);         // [512]
    float* q      = (float*)(sm + SM_Q);         // [512]
    float* p      = (float*)(sm + SM_P);         // [128]
    float* su     = (float*)(sm + SM_SU);        // [128]
    float* cred   = (float*)(sm + SM_CRED);      // [16]

    int g = blockIdx.x, b = g >> 2;
    unsigned rank;
    asm("mov.u32 %0, %%cluster_ctarank;" : "=r"(rank));
    int row0 = (int)rank * 128;
    int t = threadIdx.x, warp = t >> 5, lane = t & 31;
    unsigned sb = smem_u32(sm);

    // prologue: bf16 E tile gmem -> smem (raw 128KB copy)
    {
        const uint4* Eg4 = (const uint4*)(g_Ebf + ((size_t)b * NN + row0) * 256);
        uint4* Es4 = (uint4*)Eu;
        #pragma unroll
        for (int i = t; i < 8192; i += PTHREADS) Es4[i] = Eg4[i];
    }
    if (t < 512) { w[t] = 1.f; q[t] = 1.f; }
    if (t < 128) p[t] = 1.f;
    __syncthreads();

    for (int it = 0; it < ITERS; it++) {
        float wreg[16];
        #pragma unroll
        for (int k = 0; k < 8; k++) {
            float2 wp = *(const float2*)&w[2*lane + 64*k];
            wreg[2*k] = wp.x; wreg[2*k+1] = wp.y;
        }
        float colacc[16];
        #pragma unroll
        for (int i = 0; i < 16; i++) colacc[i] = 0.f;

        #pragma unroll
        for (int rg = 0; rg < 4; rg++) {
            int rowA = warp * 8 + rg * 2;
            int rowB = rowA + 1;
            const unsigned* EA = &Eu[rowA * 256];
            const unsigned* EB = &Eu[rowB * 256];
            unsigned ea[8], eb[8];
            #pragma unroll
            for (int k = 0; k < 8; k++) ea[k] = EA[lane + 32*k];
            #pragma unroll
            for (int k = 0; k < 8; k++) eb[k] = EB[lane + 32*k];

            float dA0=0.f, dA1=0.f, dB0=0.f, dB1=0.f;
            #pragma unroll
            for (int k = 0; k < 8; k++) {
                dA0 += __uint_as_float(ea[k] << 16)         * wreg[2*k];
                dA1 += __uint_as_float(ea[k] & 0xffff0000u) * wreg[2*k+1];
                dB0 += __uint_as_float(eb[k] << 16)         * wreg[2*k];
                dB1 += __uint_as_float(eb[k] & 0xffff0000u) * wreg[2*k+1];
            }
            float dA = dA0 + dA1, dB = dB0 + dB1;
            #pragma unroll
            for (int o = 16; o; o >>= 1) {
                dA += __shfl_xor_sync(0xffffffffu, dA, o);
                dB += __shfl_xor_sync(0xffffffffu, dB, o);
            }
            float pA = p[rowA], pB = p[rowB];
            float uA = MARG / (pA * dA + TINYF);
            float uB = MARG / (pB * dB + TINYF);
            float pnA = pA * uA, pnB = pB * uB;
            if (lane == 0) {
                p[rowA] = pnA; p[rowB] = pnB;
                if (it == ITERS - 1) { su[rowA] = uA * pnA; su[rowB] = uB * pnB; }
            }
            #pragma unroll
            for (int k = 0; k < 8; k++) {
                colacc[2*k]   += __uint_as_float(ea[k] << 16)         * pnA
                               + __uint_as_float(eb[k] << 16)         * pnB;
                colacc[2*k+1] += __uint_as_float(ea[k] & 0xffff0000u) * pnA
                               + __uint_as_float(eb[k] & 0xffff0000u) * pnB;
            }
        }
        #pragma unroll
        for (int k = 0; k < 8; k++)
            *(float2*)&colp[warp * 512 + 2*lane + 64*k] =
                make_float2(colacc[2*k], colacc[2*k+1]);
        __syncthreads();
        if (t < 512) {
            float s = 0.f;
            #pragma unroll
            for (int j = 0; j < 16; j++) s += colp[j * 512 + t];
            colr[(it & 1) * 512 + t] = s;
        }
        CLUSTER_BAR();
        if (t < 512) {
            unsigned addr = sb + SM_COLR + (unsigned)(it & 1) * 2048 + t * 4;
            float s0 = dsmem_ld(addr, 0);
            float s1 = dsmem_ld(addr, 1);
            float s2 = dsmem_ld(addr, 2);
            float s3 = dsmem_ld(addr, 3);
            float tot = (s0 + s1) + (s2 + s3);
            float qold = q[t];
            float v = MARG / (qold * tot + TINYF);
            float qn = qold * v;
            q[t] = qn;
            w[t] = qn * v;
        }
        __syncthreads();
    }

    // final: e = expf(-10*C) fp32 (full precision for pi); cost = sum(pi*C)
    size_t base = ((size_t)b * NN + row0) * NN;
    float csum = 0.f;
    for (int r = 0; r < 8; r++) {
        int row = warp * 8 + r;
        float s_u = su[row];
        const float4* C4 = (const float4*)(C + base + (size_t)row * NN);
        float4*       P4 = (float4*)(pi + base + (size_t)row * NN);
        #pragma unroll
        for (int k = 0; k < 4; k++) {
            int idx = lane + 32*k;
            float4 cc = C4[idx];
            float4 wv = *(const float4*)&w[4*lane + 128*k];
            float4 pv;
            pv.x = __expf(-INV_EPS*cc.x) * s_u * wv.x;
            pv.y = __expf(-INV_EPS*cc.y) * s_u * wv.y;
            pv.z = __expf(-INV_EPS*cc.z) * s_u * wv.z;
            pv.w = __expf(-INV_EPS*cc.w) * s_u * wv.w;
            csum += pv.x*cc.x + pv.y*cc.y + pv.z*cc.z + pv.w*cc.w;
            asm volatile("st.global.cs.v4.f32 [%0], {%1,%2,%3,%4};"
                         :: "l"(P4 + idx), "f"(pv.x), "f"(pv.y), "f"(pv.z), "f"(pv.w)
                         : "memory");
        }
    }
    #pragma unroll
    for (int o = 16; o; o >>= 1) csum += __shfl_xor_sync(0xffffffffu, csum, o);
    if (lane == 0) cred[warp] = csum;
    __syncthreads();
    if (t == 0) {
        float s = 0.f;
        #pragma unroll
        for (int i = 0; i < 16; i++) s += cred[i];
        cred[0] = s;
    }
    CLUSTER_BAR();
    if (rank == 0 && t == 0) {
        unsigned addr = sb + SM_CRED;
        float s0 = dsmem_ld(addr, 0);
        float s1 = dsmem_ld(addr, 1);
        float s2 = dsmem_ld(addr, 2);
        float s3 = dsmem_ld(addr, 3);
        cost[b] = (s0 + s1) + (s2 + s3);
    }
    CLUSTER_BAR();
}

// ---------------- launch ------------------------------------------------------
extern "C" void kernel_launch(void* const* d_in, const int* in_sizes, int n_in,
                              void* d_out, int out_size) {
    const float* x = (const float*)d_in[0];
    const float* y = (const float*)d_in[1];
    float* out  = (float*)d_out;
    float* cost = out;
    float* pi   = out + NB;
    float* C    = out + NB + (size_t)NB * NN * NN;

    static int smem_set = 0;
    if (!smem_set) {
        cudaFuncSetAttribute(sink_kernel,
                             cudaFuncAttributeMaxDynamicSharedMemorySize, SM_TOT);
        cudaFuncSetAttribute(gemm_kernel,
                             cudaFuncAttributeMaxDynamicSharedMemorySize, GTOT);
        smem_set = 1;
    }

    gemm_kernel<<<dim3(8, 4, NB), 256, GTOT>>>(C, x, y);
    sink_kernel<<<PGRID, PTHREADS, SM_TOT>>>(cost, pi, C);
}